// round 2
// baseline (speedup 1.0000x reference)
#include <cuda_runtime.h>
#include <math.h>

// Problem constants
#define BB 64      // batch
#define TT 256     // time steps
#define HH 512     // hidden
#define NG 3584    // 7*H gate width
#define KK 512     // per-half K (x part / h part each 512)

// ---------------- scratch (no allocations allowed) ----------------
// GX[m][n], m = b*TT + t  : x-part pre-activations + bias, all timesteps
__device__ float g_gx[(long long)BB * TT * NG];   // 58,720,256 floats (~224MB)
// GH[b][n] : h-part pre-activations for current step
__device__ float g_gh[BB * NG];                   // 229,376 floats
// persistent cell states
__device__ float g_cf[BB * HH];
__device__ float g_cb[BB * HH];

// ---------------- Phase 1: GX = X @ W[0:512] + b  (M=16384,K=512,N=3584) ----
#define BM1 128
#define BN1 64
#define BK1 8

__global__ __launch_bounds__(256) void gemm_gx_kernel(
    const float* __restrict__ X,   // [B*T, 512] (natural layout of seq_type_embed)
    const float* __restrict__ W,   // [1024, 3584]
    const float* __restrict__ bias,// [3584]
    float* __restrict__ GX)        // [B*T, 3584]
{
    __shared__ float As[BK1][BM1 + 4];  // stored transposed [k][m], padded
    __shared__ float Bs[BK1][BN1];

    const int tid = threadIdx.x;
    const int bm = blockIdx.y * BM1;
    const int bn = blockIdx.x * BN1;
    const int ty = tid >> 4;        // 0..15
    const int tx = tid & 15;        // 0..15

    // A load map: thread -> (row, 4 consecutive k)
    const int arow = tid >> 1;            // 0..127
    const int acol = (tid & 1) * 4;       // 0 or 4
    // B load map: thread -> (k, 2 consecutive n)
    const int brow = tid >> 5;            // 0..7
    const int bcol = (tid & 31) * 2;      // 0..62

    float acc[8][4];
#pragma unroll
    for (int i = 0; i < 8; i++)
#pragma unroll
        for (int j = 0; j < 4; j++) acc[i][j] = 0.f;

    for (int k0 = 0; k0 < KK; k0 += BK1) {
        float4 av = *(const float4*)&X[(long long)(bm + arow) * KK + k0 + acol];
        As[acol + 0][arow] = av.x;
        As[acol + 1][arow] = av.y;
        As[acol + 2][arow] = av.z;
        As[acol + 3][arow] = av.w;
        float2 bv = *(const float2*)&W[(long long)(k0 + brow) * NG + bn + bcol];
        Bs[brow][bcol + 0] = bv.x;
        Bs[brow][bcol + 1] = bv.y;
        __syncthreads();

#pragma unroll
        for (int kk = 0; kk < BK1; kk++) {
            float a[8], b[4];
#pragma unroll
            for (int i = 0; i < 8; i++) a[i] = As[kk][ty * 8 + i];
#pragma unroll
            for (int j = 0; j < 4; j++) b[j] = Bs[kk][tx * 4 + j];
#pragma unroll
            for (int i = 0; i < 8; i++)
#pragma unroll
                for (int j = 0; j < 4; j++) acc[i][j] = fmaf(a[i], b[j], acc[i][j]);
        }
        __syncthreads();
    }

#pragma unroll
    for (int i = 0; i < 8; i++) {
        const long long m = bm + ty * 8 + i;
#pragma unroll
        for (int j = 0; j < 4; j++) {
            const int n = bn + tx * 4 + j;
            GX[m * NG + n] = acc[i][j] + bias[n];
        }
    }
}

// ---------------- Phase 2a: GH = h_{t-1} @ W[512:1024]  (M=64,K=512,N=3584) --
#define BM2 64
#define BN2 32
#define BK2 16

__global__ __launch_bounds__(256) void gemm_gh_kernel(
    const float* __restrict__ Hts, // d_out h region: [B, T, H]
    const float* __restrict__ W,   // [1024, 3584]
    float* __restrict__ GH,        // [64, 3584]
    int t)
{
    const int tid = threadIdx.x;
    const int bn = blockIdx.x * BN2;
    const int ty = tid >> 4;       // 0..15 -> 4 rows each
    const int tx = tid & 15;       // 0..15 -> 2 cols each

    if (t == 0) {
        // h_{-1} = 0 -> GH = 0
#pragma unroll
        for (int i = 0; i < 4; i++) {
            const int row = ty * 4 + i;
#pragma unroll
            for (int j = 0; j < 2; j++) {
                GH[row * NG + bn + tx * 2 + j] = 0.f;
            }
        }
        return;
    }

    __shared__ float Hs[BK2][BM2 + 1];  // transposed [k][b], padded
    __shared__ float Ws[BK2][BN2];

    // H load map: thread -> (b row, 4 consecutive k)
    const int hrow = tid >> 2;           // 0..63
    const int hcol = (tid & 3) * 4;      // 0,4,8,12
    // W load map
    const int wrow = tid >> 4;           // 0..15
    const int wcol = (tid & 15) * 2;     // 0..30

    float acc[4][2];
#pragma unroll
    for (int i = 0; i < 4; i++) { acc[i][0] = 0.f; acc[i][1] = 0.f; }

    const long long hbase = ((long long)hrow * TT + (t - 1)) * HH;

    for (int k0 = 0; k0 < KK; k0 += BK2) {
        float4 hv = *(const float4*)&Hts[hbase + k0 + hcol];
        Hs[hcol + 0][hrow] = hv.x;
        Hs[hcol + 1][hrow] = hv.y;
        Hs[hcol + 2][hrow] = hv.z;
        Hs[hcol + 3][hrow] = hv.w;
        float2 wv = *(const float2*)&W[(long long)(KK + k0 + wrow) * NG + bn + wcol];
        Ws[wrow][wcol + 0] = wv.x;
        Ws[wrow][wcol + 1] = wv.y;
        __syncthreads();

#pragma unroll
        for (int kk = 0; kk < BK2; kk++) {
            float a[4], b[2];
#pragma unroll
            for (int i = 0; i < 4; i++) a[i] = Hs[kk][ty * 4 + i];
            b[0] = Ws[kk][tx * 2 + 0];
            b[1] = Ws[kk][tx * 2 + 1];
#pragma unroll
            for (int i = 0; i < 4; i++) {
                acc[i][0] = fmaf(a[i], b[0], acc[i][0]);
                acc[i][1] = fmaf(a[i], b[1], acc[i][1]);
            }
        }
        __syncthreads();
    }

#pragma unroll
    for (int i = 0; i < 4; i++) {
        const int row = ty * 4 + i;
#pragma unroll
        for (int j = 0; j < 2; j++) {
            GH[row * NG + bn + tx * 2 + j] = acc[i][j];
        }
    }
}

// ---------------- Phase 2b: cell update + outputs ----------------
__device__ __forceinline__ float sigmoidf_(float x) {
    return 1.f / (1.f + expf(-x));
}
__device__ __forceinline__ float softplusf_(float x) {
    // stable: max(x,0) + log1p(exp(-|x|))
    return fmaxf(x, 0.f) + log1pf(expf(-fabsf(x)));
}

__global__ __launch_bounds__(256) void cell_update_kernel(
    const float* __restrict__ GX,
    const float* __restrict__ GH,
    const float* __restrict__ dtime,  // [B, T]
    float* __restrict__ cf,
    float* __restrict__ cb,
    float* __restrict__ out,          // d_out: h_ts[B,T,H] then decay[B,T,4,H]
    int t)
{
    const int idx = blockIdx.x * blockDim.x + threadIdx.x;  // 0..32767
    const int b = idx >> 9;          // /512
    const int c = idx & (HH - 1);

    const float* gxr = &GX[((long long)b * TT + t) * NG];
    const float* ghr = &GH[(long long)b * NG];

    float g0 = gxr[0 * HH + c] + ghr[0 * HH + c];
    float g1 = gxr[1 * HH + c] + ghr[1 * HH + c];
    float g2 = gxr[2 * HH + c] + ghr[2 * HH + c];
    float g3 = gxr[3 * HH + c] + ghr[3 * HH + c];
    float g4 = gxr[4 * HH + c] + ghr[4 * HH + c];
    float g5 = gxr[5 * HH + c] + ghr[5 * HH + c];
    float g6 = gxr[6 * HH + c] + ghr[6 * HH + c];

    const float gate_i  = sigmoidf_(g0);
    const float gate_f  = sigmoidf_(g1);
    const float gate_o  = sigmoidf_(g2);
    const float gate_ib = sigmoidf_(g3);
    const float gate_fb = sigmoidf_(g4);
    const float gate_d  = softplusf_(g5);
    const float z       = tanhf(g6);

    const float cfv = (t == 0) ? 0.f : cf[idx];
    const float cbv = (t == 0) ? 0.f : cb[idx];

    const float c_t   = gate_f  * cfv + gate_i  * z;
    const float cb_t  = gate_fb * cbv + gate_ib * z;
    const float dt    = dtime[b * TT + t];
    const float cfn   = cb_t + (c_t - cb_t) * expf(-gate_d * dt);
    const float h_t   = gate_o * tanhf(cfn);

    cf[idx] = cfn;
    cb[idx] = cb_t;

    // h_ts[b][t][c]
    out[((long long)b * TT + t) * HH + c] = h_t;
    // decay_states[b][t][s][c], s in {c_t, c_bar_t, gate_decay, gate_output}
    float* dec = out + (long long)BB * TT * HH + (((long long)b * TT + t) * 4) * HH + c;
    dec[0 * HH] = c_t;
    dec[1 * HH] = cb_t;
    dec[2 * HH] = gate_d;
    dec[3 * HH] = gate_o;
}

// ---------------- launch ----------------
extern "C" void kernel_launch(void* const* d_in, const int* in_sizes, int n_in,
                              void* d_out, int out_size) {
    (void)in_sizes; (void)n_in; (void)out_size;
    const float* X     = (const float*)d_in[0];  // seq_type_embed [B,T,H]
    const float* dtime = (const float*)d_in[1];  // [B,T]
    const float* W     = (const float*)d_in[2];  // [2H, 7H]
    const float* bias  = (const float*)d_in[3];  // [7H]
    float* out = (float*)d_out;

    float *GX, *GH, *CF, *CB;
    cudaGetSymbolAddress((void**)&GX, g_gx);
    cudaGetSymbolAddress((void**)&GH, g_gh);
    cudaGetSymbolAddress((void**)&CF, g_cf);
    cudaGetSymbolAddress((void**)&CB, g_cb);

    // Phase 1: precompute x-part pre-activations for all timesteps
    dim3 grid1(NG / BN1, (BB * TT) / BM1);   // (56, 128)
    gemm_gx_kernel<<<grid1, 256>>>(X, W, bias, GX);

    // Phase 2: sequential scan
    for (int t = 0; t < TT; t++) {
        gemm_gh_kernel<<<NG / BN2, 256>>>(out, W, GH, t);       // 112 blocks
        cell_update_kernel<<<(BB * HH) / 256, 256>>>(GX, GH, dtime, CF, CB, out, t); // 128 blocks
    }
}

// round 3
// speedup vs baseline: 1.1967x; 1.1967x over previous
#include <cuda_runtime.h>
#include <math.h>

// Problem constants
#define BB 64      // batch
#define TT 256     // time steps
#define HH 512     // hidden
#define NG 3584    // 7*H gate width
#define KK 512     // per-half K (x part / h part each 512)

typedef unsigned long long u64;

// ---------------- packed fp32x2 helpers (sm_103a FFMA2) ----------------
__device__ __forceinline__ u64 pack2(float x, float y) {
    u64 r; asm("mov.b64 %0,{%1,%2};" : "=l"(r) : "f"(x), "f"(y)); return r;
}
__device__ __forceinline__ void ffma2(u64 &d, u64 a, u64 b) {
    asm("fma.rn.f32x2 %0,%1,%2,%0;" : "+l"(d) : "l"(a), "l"(b));
}
__device__ __forceinline__ float2 unpack2(u64 v) {
    float2 f; asm("mov.b64 {%0,%1},%2;" : "=f"(f.x), "=f"(f.y) : "l"(v)); return f;
}

// ---------------- scratch (no allocations allowed) ----------------
// GX layout: [t][b][n], n = j*512 + c  (x-part pre-activations + bias)
__device__ float g_gx[(long long)BB * TT * NG];   // ~224MB
__device__ unsigned g_bar_count = 0;
__device__ unsigned g_bar_gen = 0;

// ---------------- Phase 1: GX = X @ W[0:512] + b  (M=16384,K=512,N=3584) ----
#define BM1 128
#define BN1 64
#define BK1 8

__global__ __launch_bounds__(256) void gemm_gx_kernel(
    const float* __restrict__ X,   // [B*T, 512]
    const float* __restrict__ W,   // [1024, 3584]
    const float* __restrict__ bias,// [3584]
    float* __restrict__ GX)        // [T][B][3584]
{
    __shared__ float As[BK1][BM1 + 4];
    __shared__ float Bs[BK1][BN1];

    const int tid = threadIdx.x;
    const int bm = blockIdx.y * BM1;
    const int bn = blockIdx.x * BN1;
    const int ty = tid >> 4;        // 0..15
    const int tx = tid & 15;        // 0..15

    const int arow = tid >> 1;
    const int acol = (tid & 1) * 4;
    const int brow = tid >> 5;
    const int bcol = (tid & 31) * 2;

    u64 acc[8][2];
#pragma unroll
    for (int i = 0; i < 8; i++) { acc[i][0] = 0ull; acc[i][1] = 0ull; }

    for (int k0 = 0; k0 < KK; k0 += BK1) {
        float4 av = *(const float4*)&X[(long long)(bm + arow) * KK + k0 + acol];
        As[acol + 0][arow] = av.x;
        As[acol + 1][arow] = av.y;
        As[acol + 2][arow] = av.z;
        As[acol + 3][arow] = av.w;
        float2 bv = *(const float2*)&W[(long long)(k0 + brow) * NG + bn + bcol];
        Bs[brow][bcol + 0] = bv.x;
        Bs[brow][bcol + 1] = bv.y;
        __syncthreads();

#pragma unroll
        for (int kk = 0; kk < BK1; kk++) {
            ulonglong2 bv2 = *(const ulonglong2*)&Bs[kk][tx * 4];
#pragma unroll
            for (int i = 0; i < 8; i++) {
                float a = As[kk][ty * 8 + i];
                u64 a2 = pack2(a, a);
                ffma2(acc[i][0], a2, bv2.x);
                ffma2(acc[i][1], a2, bv2.y);
            }
        }
        __syncthreads();
    }

#pragma unroll
    for (int i = 0; i < 8; i++) {
        const int m = bm + ty * 8 + i;
        const int b = m >> 8;        // m = b*TT + t
        const int t = m & 255;
        float* row = &GX[((long long)t * BB + b) * NG];
        const int n = bn + tx * 4;
        float2 r0 = unpack2(acc[i][0]);
        float2 r1 = unpack2(acc[i][1]);
        row[n + 0] = r0.x + bias[n + 0];
        row[n + 1] = r0.y + bias[n + 1];
        row[n + 2] = r1.x + bias[n + 2];
        row[n + 3] = r1.y + bias[n + 3];
    }
}

// ---------------- Phase 2: persistent scan kernel ----------------
// 128 CTAs x 256 threads. CTA blk owns h-columns [blk*4, blk*4+4).
// Thread tid: b = tid>>2 (batch row), cc = tid&3 (column within slice).
// Each thread keeps all 7 gate accumulators + cell state in registers.
// SMEM: Ws [512][32] (28 gate cols padded to 32, layout k*32 + cc*8 + j)
//       hs [64][516] (h_{t-1} staged, padded to kill bank conflicts)

#define NBLK 128
#define HS_STRIDE 516
#define WS_FLOATS (KK * 32)
#define SMEM_BYTES ((WS_FLOATS + BB * HS_STRIDE) * 4)

__device__ __forceinline__ void grid_barrier() {
    __threadfence();
    __syncthreads();
    if (threadIdx.x == 0) {
        unsigned gen = *(volatile unsigned*)&g_bar_gen;
        unsigned arrived = atomicAdd(&g_bar_count, 1u);
        if (arrived == NBLK - 1) {
            g_bar_count = 0;
            __threadfence();
            *(volatile unsigned*)&g_bar_gen = gen + 1;
        } else {
            while (*(volatile unsigned*)&g_bar_gen == gen) {}
        }
    }
    __syncthreads();
}

__device__ __forceinline__ float sigmoidf_(float x) {
    return 1.f / (1.f + expf(-x));
}
__device__ __forceinline__ float softplusf_(float x) {
    return fmaxf(x, 0.f) + log1pf(expf(-fabsf(x)));
}

__global__ __launch_bounds__(256, 1) void scan_kernel(
    const float* __restrict__ GX,    // [T][B][3584]
    const float* __restrict__ dtime, // [B,T]
    const float* __restrict__ W,     // [1024, 3584]
    float* out)                      // h_ts[B,T,H] then decay[B,T,4,H]
{
    extern __shared__ float smem[];
    float* Ws = smem;                  // [512][32]
    float* hs = smem + WS_FLOATS;      // [64][516]

    const int tid = threadIdx.x;
    const int blk = blockIdx.x;
    const int c0 = blk * 4;
    const int b = tid >> 2;
    const int cc = tid & 3;
    const int c = c0 + cc;

    // One-time: load this CTA's W_h slice into SMEM.
    // Ws[k*32 + cc2*8 + j] = W[(512+k)][j*512 + c0 + cc2], j<7; j==7 slot = 0
    for (int i = tid; i < WS_FLOATS; i += 256) {
        int k = i >> 5;
        int r = i & 31;
        int cc2 = r >> 3;
        int j = r & 7;
        float v = 0.f;
        if (j < 7) v = W[(long long)(KK + k) * NG + j * HH + c0 + cc2];
        Ws[i] = v;
    }
    __syncthreads();

    float cf_r = 0.f;   // c_func state for (b, c)
    float cb_r = 0.f;   // c_bar state

    const u64* Ws8base = (const u64*)Ws + cc * 4;
    const float* hrow = hs + b * HS_STRIDE;
    const long long DEC0 = (long long)BB * TT * HH;

    for (int t = 0; t < TT; t++) {
        // x-part gate values (independent of h; issue early to hide DRAM latency)
        const float* gx = GX + ((long long)t * BB + b) * NG + c;
        float x0 = gx[0 * HH];
        float x1 = gx[1 * HH];
        float x2 = gx[2 * HH];
        float x3 = gx[3 * HH];
        float x4 = gx[4 * HH];
        float x5 = gx[5 * HH];
        float x6 = gx[6 * HH];

        u64 acc0 = 0ull, acc1 = 0ull, acc2 = 0ull, acc3 = 0ull;

        if (t > 0) {
            // stage h_{t-1} into SMEM: 64 rows x 512 floats
#pragma unroll
            for (int i = 0; i < 32; i++) {
                int lin = i * 256 + tid;        // float4 index 0..8191
                int bb = lin >> 7;
                int q = lin & 127;
                float4 v = *(const float4*)&out[((long long)bb * TT + (t - 1)) * HH + q * 4];
                *(float4*)&hs[bb * HS_STRIDE + q * 4] = v;
            }
            __syncthreads();

            // GH[b][7 gates for column c] via packed FFMA2
#pragma unroll 4
            for (int k = 0; k < KK; k++) {
                float a = hrow[k];
                u64 a2 = pack2(a, a);
                const u64* wr = Ws8base + (k << 4);
                ulonglong2 w01 = *(const ulonglong2*)(wr);
                ulonglong2 w23 = *(const ulonglong2*)(wr + 2);
                ffma2(acc0, a2, w01.x);
                ffma2(acc1, a2, w01.y);
                ffma2(acc2, a2, w23.x);
                ffma2(acc3, a2, w23.y);
            }
        }

        float2 p01 = unpack2(acc0);
        float2 p23 = unpack2(acc1);
        float2 p45 = unpack2(acc2);
        float2 p6x = unpack2(acc3);

        const float g0 = x0 + p01.x;
        const float g1 = x1 + p01.y;
        const float g2 = x2 + p23.x;
        const float g3 = x3 + p23.y;
        const float g4 = x4 + p45.x;
        const float g5 = x5 + p45.y;
        const float g6 = x6 + p6x.x;

        const float gate_i  = sigmoidf_(g0);
        const float gate_f  = sigmoidf_(g1);
        const float gate_o  = sigmoidf_(g2);
        const float gate_ib = sigmoidf_(g3);
        const float gate_fb = sigmoidf_(g4);
        const float gate_d  = softplusf_(g5);
        const float z       = tanhf(g6);

        const float c_t  = gate_f  * cf_r + gate_i  * z;
        const float cb_t = gate_fb * cb_r + gate_ib * z;
        const float dt   = dtime[b * TT + t];
        const float cfn  = cb_t + (c_t - cb_t) * expf(-gate_d * dt);
        const float h_t  = gate_o * tanhf(cfn);

        cf_r = cfn;
        cb_r = cb_t;

        // h_ts[b][t][c]
        out[((long long)b * TT + t) * HH + c] = h_t;
        // decay_states[b][t][s][c]
        float* dec = out + DEC0 + ((long long)(b * TT + t) * 4) * HH + c;
        dec[0 * HH] = c_t;
        dec[1 * HH] = cb_t;
        dec[2 * HH] = gate_d;
        dec[3 * HH] = gate_o;

        // make h_t visible chip-wide before anyone reads step t
        grid_barrier();
    }
}

// ---------------- launch ----------------
extern "C" void kernel_launch(void* const* d_in, const int* in_sizes, int n_in,
                              void* d_out, int out_size) {
    (void)in_sizes; (void)n_in; (void)out_size;
    const float* X     = (const float*)d_in[0];  // seq_type_embed [B,T,H]
    const float* dtime = (const float*)d_in[1];  // [B,T]
    const float* W     = (const float*)d_in[2];  // [2H, 7H]
    const float* bias  = (const float*)d_in[3];  // [7H]
    float* out = (float*)d_out;

    float* GX;
    cudaGetSymbolAddress((void**)&GX, g_gx);

    // Phase 1: precompute x-part pre-activations for all timesteps
    dim3 grid1(NG / BN1, (BB * TT) / BM1);   // (56, 128)
    gemm_gx_kernel<<<grid1, 256>>>(X, W, bias, GX);

    // Phase 2: one persistent kernel for the whole scan
    cudaFuncSetAttribute(scan_kernel, cudaFuncAttributeMaxDynamicSharedMemorySize,
                         SMEM_BYTES);
    scan_kernel<<<NBLK, 256, SMEM_BYTES>>>(GX, dtime, W, out);
}